// round 10
// baseline (speedup 1.0000x reference)
#include <cuda_runtime.h>

#define DATA_NUM 1024
#define CLS_NUM  32000
#define NB       4096            // histogram bins (both levels)
#define NT       256             // threads per CTA
#define BPT      (NB / NT)       // 16 bins per thread
#define RANGE2   140.0f          // log2-domain window below the M2 bound
#define CAP      4096            // stash capacity for crossing-bin elements
#define LOG2E    1.4426950408889634f
#define LN2      0.6931471805599453f

// Guaranteed-scalar 32-bit load for the tiny h vectors.
__device__ __forceinline__ float vload(const float* p) {
    return *(const volatile float*)p;
}

// Block-wide sum via shared-memory tree (no shuffles). red: NT floats.
__device__ float block_sum(float v, float* red) {
    int tid = threadIdx.x;
    __syncthreads();
    red[tid] = v;
    __syncthreads();
#pragma unroll
    for (int s = NT / 2; s > 0; s >>= 1) {
        if (tid < s) red[tid] += red[tid + s];
        __syncthreads();
    }
    float r = red[0];
    __syncthreads();
    return r;
}

// Find bin where ascending cumulative mass crosses `target`.
// *s_bin = crossing bin, *s_cdf = exclusive prefix mass of that bin.
__device__ void find_crossing(const float* hist, float* red, float target,
                              int* s_bin, float* s_cdf) {
    int tid = threadIdx.x;
    __syncthreads();
    if (tid == 0) { *s_bin = NB - 1; *s_cdf = 0.f; }   // safe default
    float h[BPT];
    float s = 0.f;
#pragma unroll
    for (int i = 0; i < BPT; i++) { h[i] = hist[tid * BPT + i]; s += h[i]; }
    red[tid] = s;
    __syncthreads();
    if (tid == 0) {                  // exclusive scan of NT partials
        float c = 0.f;
        for (int i = 0; i < NT; i++) { float t = red[i]; red[i] = c; c += t; }
    }
    __syncthreads();
    float c = red[tid];
#pragma unroll
    for (int i = 0; i < BPT; i++) {
        if (c < target && c + h[i] >= target) { *s_bin = tid * BPT + i; *s_cdf = c; }
        c += h[i];
    }
    __syncthreads();
}

// ---------------------------------------------------------------------------
__global__ void zero_out(float* out) { out[0] = 0.f; }

// One CTA per data row. All exponentials in base-2 (single-MUFU exp2f).
__global__ void __launch_bounds__(NT) akl_kernel(
    const float* h1, const float* e1,
    const float* h3, const float* e3, float* out)
{
    __shared__ float hist[NB];
    __shared__ float red[NT];
    __shared__ float st_l2[CAP];    // log2-domain teacher logit
    __shared__ float st_u2[CAP];
    __shared__ float st_gap[CAP];
    __shared__ int   s_cnt;
    __shared__ float s_cdf1, s_cdf2;
    __shared__ int   s_b1,   s_b2;

    const int row = blockIdx.x;
    const int tid = threadIdx.x;

    // Row coefficients, pre-scaled by log2(e): all logits live in log2 domain.
    const float a1 = vload(h1 + 2 * row) * LOG2E, b1c = vload(h1 + 2 * row + 1) * LOG2E;
    const float a3 = vload(h3 + 2 * row) * LOG2E, b3c = vload(h3 + 2 * row + 1) * LOG2E;
    // Analytic bound: |l2| <= ||h'|| * max||e_j||, max 2-D N(0,1) norm over
    // 32k draws < 6 w.o.p. Softmax shift-invariance makes any bound exact.
    const float M1 = 6.0f * sqrtf(a1 * a1 + b1c * b1c);
    const float M2 = 6.0f * sqrtf(a3 * a3 + b3c * b3c);
    const float lo   = M2 - RANGE2;
    const float invw = (float)NB / RANGE2;

    const float2* e1v = (const float2*)e1;
    const float2* e3v = (const float2*)e3;

    for (int b = tid; b < NB; b += NT) hist[b] = 0.f;
    if (tid == 0) s_cnt = 0;
    __syncthreads();

    // ---- Pass 1: partition sums, KL linear terms, level-1 histogram of u2
    float Z1 = 0.f, Z2 = 0.f, S1 = 0.f, S2 = 0.f;
#pragma unroll 2
    for (int j = tid; j < CLS_NUM; j += NT) {
        float2 v1 = __ldg(e1v + j);
        float2 v3 = __ldg(e3v + j);
        float l1 = fmaf(a1, v1.x, b1c * v1.y);   // log2-domain logits
        float l2 = fmaf(a3, v3.x, b3c * v3.y);
        float u1 = exp2f(l1 - M1);
        float u2 = exp2f(l2 - M2);
        Z1 += u1; Z2 += u2;
        float dl = l2 - l1;                      // log2-domain diff
        S2 = fmaf(u2,  dl, S2);
        S1 = fmaf(u1, -dl, S1);
        int b = (int)((l2 - lo) * invw);
        b = max(0, min(NB - 1, b));
        atomicAdd(&hist[b], u2);
    }
    Z1 = block_sum(Z1, red);
    Z2 = block_sum(Z2, red);
    S1 = block_sum(S1, red);
    S2 = block_sum(S2, red);
    const float halfZ2 = 0.5f * Z2;

    // ---- Level-1 crossing bin
    find_crossing(hist, red, halfZ2, &s_b1, &s_cdf1);
    const int   b1   = s_b1;
    const float cdf1 = s_cdf1;
    __syncthreads();

    // ---- Pass 2: gap sums; stash crossing-bin elements
    const float invZ1 = 1.0f / Z1, invZ2 = 1.0f / Z2;
    float gh = 0.f, gt = 0.f;
#pragma unroll 2
    for (int j = tid; j < CLS_NUM; j += NT) {
        float2 v1 = __ldg(e1v + j);
        float2 v3 = __ldg(e3v + j);
        float l1 = fmaf(a1, v1.x, b1c * v1.y);
        float l2 = fmaf(a3, v3.x, b3c * v3.y);
        float u2 = exp2f(l2 - M2);
        float p1 = exp2f(l1 - M1) * invZ1;
        float p2 = u2 * invZ2;
        float gap = fabsf(p2 - p1);
        int b = (int)((l2 - lo) * invw);
        b = max(0, min(NB - 1, b));
        if (b < b1)      gt += gap;
        else if (b > b1) gh += gap;
        else {
            int idx = atomicAdd(&s_cnt, 1);
            if (idx < CAP) { st_l2[idx] = l2; st_u2[idx] = u2; st_gap[idx] = gap; }
            else { if (cdf1 + u2 < halfZ2) gt += gap; else gh += gap; }
        }
    }
    __syncthreads();

    // ---- Level-2: sub-histogram over the stash only (O(m), smem-only)
    const int m = min(s_cnt, CAP);
    const float w1    = RANGE2 / (float)NB;
    const float lo1   = lo + (float)b1 * w1;
    const float invw2 = (float)NB / w1;

    for (int b = tid; b < NB; b += NT) hist[b] = 0.f;
    __syncthreads();
    for (int i = tid; i < m; i += NT) {
        int s = (int)((st_l2[i] - lo1) * invw2);
        s = max(0, min(NB - 1, s));
        atomicAdd(&hist[s], st_u2[i]);
    }
    find_crossing(hist, red, halfZ2 - cdf1, &s_b2, &s_cdf2);
    const int   b2   = s_b2;
    const float cdf2 = cdf1 + s_cdf2;   // mass strictly below the final sub-bin
    __syncthreads();

    // ---- Classify stash by sub-bin (tie-break inside final sub-bin by mass)
    for (int i = tid; i < m; i += NT) {
        int s = (int)((st_l2[i] - lo1) * invw2);
        s = max(0, min(NB - 1, s));
        bool tail;
        if (s != b2) tail = (s < b2);
        else         tail = (cdf2 + st_u2[i]) < halfZ2;
        if (tail) gt += st_gap[i]; else gh += st_gap[i];
    }
    gh = block_sum(gh, red);
    gt = block_sum(gt, red);

    if (tid == 0) {
        // Convert log2-domain sums to nats:
        // C21 = ln2*(M2-M1) + ln(Z2) - ln(Z1);  fkl = ln2*S2/Z2 - C21; rkl sym.
        float C21 = LN2 * (M2 - M1) + (__logf(Z2) - __logf(Z1));
        float fkl = LN2 * S2 / Z2 - C21;
        float rkl = LN2 * S1 / Z1 + C21;
        float denom = gh + gt;
        float akl = (gh * fkl + gt * rkl) / denom;
        atomicAdd(out, akl * (1.0f / (float)DATA_NUM));
    }
}

// ---------------------------------------------------------------------------
extern "C" void kernel_launch(void* const* d_in, const int* in_sizes, int n_in,
                              void* d_out, int out_size) {
    // Bind by size (element OR byte counts); positional fallback.
    const float *h1 = 0, *h3 = 0, *e1 = 0, *e3 = 0;
    for (int i = 0; i < n_in; i++) {
        int s = in_sizes[i];
        if (s == 2 * DATA_NUM || s == 2 * DATA_NUM * 4) {
            if (!h1) h1 = (const float*)d_in[i]; else if (!h3) h3 = (const float*)d_in[i];
        } else if (s == 2 * CLS_NUM || s == 2 * CLS_NUM * 4) {
            if (!e1) e1 = (const float*)d_in[i]; else if (!e3) e3 = (const float*)d_in[i];
        }
    }
    if (!h1 || !h3 || !e1 || !e3) {
        h1 = (const float*)d_in[0];
        e1 = (const float*)d_in[1];
        h3 = (const float*)d_in[2];
        e3 = (const float*)d_in[3];
    }

    float* out = (float*)d_out;
    zero_out<<<1, 1>>>(out);
    akl_kernel<<<DATA_NUM, NT>>>(h1, e1, h3, e3, out);
}

// round 11
// speedup vs baseline: 1.5758x; 1.5758x over previous
#include <cuda_runtime.h>

#define DATA_NUM 1024
#define CLS_NUM  32000
#define NB       4096            // histogram bins (both levels)
#define NT       256             // threads per CTA
#define BPT      (NB / NT)       // 16 bins per thread
#define RANGE2   140.0f          // log2-domain window below the M2 bound
#define CAP      4096            // stash capacity for crossing-bin elements
#define LOG2E    1.4426950408889634f
#define LN2      0.6931471805599453f

// Guaranteed-scalar 32-bit load for the tiny h vectors.
__device__ __forceinline__ float vload(const float* p) {
    return *(const volatile float*)p;
}

// Bare MUFU exponential (base 2) — fast regardless of -use_fast_math.
__device__ __forceinline__ float ex2(float x) {
    float y;
    asm("ex2.approx.f32 %0, %1;" : "=f"(y) : "f"(x));
    return y;
}

// Block-wide sum via shared-memory tree. red: NT floats.
__device__ float block_sum(float v, float* red) {
    int tid = threadIdx.x;
    __syncthreads();
    red[tid] = v;
    __syncthreads();
#pragma unroll
    for (int s = NT / 2; s > 0; s >>= 1) {
        if (tid < s) red[tid] += red[tid + s];
        __syncthreads();
    }
    float r = red[0];
    __syncthreads();
    return r;
}

// Find bin where ascending cumulative mass crosses `target`.
__device__ void find_crossing(const float* hist, float* red, float target,
                              int* s_bin, float* s_cdf) {
    int tid = threadIdx.x;
    __syncthreads();
    if (tid == 0) { *s_bin = NB - 1; *s_cdf = 0.f; }   // safe default
    float h[BPT];
    float s = 0.f;
#pragma unroll
    for (int i = 0; i < BPT; i++) { h[i] = hist[tid * BPT + i]; s += h[i]; }
    red[tid] = s;
    __syncthreads();
    if (tid == 0) {
        float c = 0.f;
        for (int i = 0; i < NT; i++) { float t = red[i]; red[i] = c; c += t; }
    }
    __syncthreads();
    float c = red[tid];
#pragma unroll
    for (int i = 0; i < BPT; i++) {
        if (c < target && c + h[i] >= target) { *s_bin = tid * BPT + i; *s_cdf = c; }
        c += h[i];
    }
    __syncthreads();
}

// ---------------------------------------------------------------------------
__global__ void zero_out(float* out) { out[0] = 0.f; }

// One CTA per data row.
__global__ void __launch_bounds__(NT) akl_kernel(
    const float* h1, const float* e1,
    const float* h3, const float* e3, float* out)
{
    __shared__ float hist[NB];
    __shared__ float red[NT];
    __shared__ float st_l2[CAP];
    __shared__ float st_u2[CAP];
    __shared__ float st_gap[CAP];
    __shared__ int   s_cnt;
    __shared__ float s_cdf1, s_cdf2;
    __shared__ int   s_b1,   s_b2;

    const int row = blockIdx.x;
    const int tid = threadIdx.x;

    // Row coefficients pre-scaled by log2(e): all logits in log2 domain.
    const float a1 = vload(h1 + 2 * row) * LOG2E, b1c = vload(h1 + 2 * row + 1) * LOG2E;
    const float a3 = vload(h3 + 2 * row) * LOG2E, b3c = vload(h3 + 2 * row + 1) * LOG2E;
    // Analytic bound: |l| <= ||h'||*max||e_j||; max 2-D N(0,1) norm over 32k
    // draws < 6 w.o.p. Softmax shift-invariance makes any bound exact.
    const float M1 = 6.0f * sqrtf(a1 * a1 + b1c * b1c);
    const float M2 = 6.0f * sqrtf(a3 * a3 + b3c * b3c);
    const float lo   = M2 - RANGE2;
    const float invw = (float)NB / RANGE2;

    const float2* e1v = (const float2*)e1;
    const float2* e3v = (const float2*)e3;

    for (int b = tid; b < NB; b += NT) hist[b] = 0.f;
    if (tid == 0) s_cnt = 0;
    __syncthreads();

    // ---- Pass 1: Z/S sums + level-1 histogram. Unroll 4, loads front-batched.
    float Z1 = 0.f, Z2 = 0.f, S1 = 0.f, S2 = 0.f;
    {
        int j = tid;
        for (; j + 3 * NT < CLS_NUM; j += 4 * NT) {
            float2 w1[4], w3[4];
#pragma unroll
            for (int u = 0; u < 4; u++) { w1[u] = __ldg(e1v + j + u * NT); }
#pragma unroll
            for (int u = 0; u < 4; u++) { w3[u] = __ldg(e3v + j + u * NT); }
#pragma unroll
            for (int u = 0; u < 4; u++) {
                float l1 = fmaf(a1, w1[u].x, b1c * w1[u].y);
                float l2 = fmaf(a3, w3[u].x, b3c * w3[u].y);
                float u1 = ex2(l1 - M1);
                float u2 = ex2(l2 - M2);
                Z1 += u1; Z2 += u2;
                float dl = l2 - l1;
                S2 = fmaf(u2,  dl, S2);
                S1 = fmaf(u1, -dl, S1);
                int b = (int)((l2 - lo) * invw);
                b = max(0, min(NB - 1, b));
                atomicAdd(&hist[b], u2);
            }
        }
        for (; j < CLS_NUM; j += NT) {
            float2 v1 = __ldg(e1v + j);
            float2 v3 = __ldg(e3v + j);
            float l1 = fmaf(a1, v1.x, b1c * v1.y);
            float l2 = fmaf(a3, v3.x, b3c * v3.y);
            float u1 = ex2(l1 - M1);
            float u2 = ex2(l2 - M2);
            Z1 += u1; Z2 += u2;
            float dl = l2 - l1;
            S2 = fmaf(u2,  dl, S2);
            S1 = fmaf(u1, -dl, S1);
            int b = (int)((l2 - lo) * invw);
            b = max(0, min(NB - 1, b));
            atomicAdd(&hist[b], u2);
        }
    }
    Z1 = block_sum(Z1, red);
    Z2 = block_sum(Z2, red);
    S1 = block_sum(S1, red);
    S2 = block_sum(S2, red);
    const float halfZ2 = 0.5f * Z2;

    // ---- Level-1 crossing bin
    find_crossing(hist, red, halfZ2, &s_b1, &s_cdf1);
    const int   b1   = s_b1;
    const float cdf1 = s_cdf1;

    // Level-2 geometry
    const float w1w   = RANGE2 / (float)NB;
    const float lo1   = lo + (float)b1 * w1w;
    const float invw2 = (float)NB / w1w;

    // reuse hist for the level-2 sub-histogram
    __syncthreads();
    for (int b = tid; b < NB; b += NT) hist[b] = 0.f;
    __syncthreads();

    // ---- Pass 2: gap sums; crossing-bin elems -> sub-hist + stash
    const float invZ1 = 1.0f / Z1, invZ2 = 1.0f / Z2;
    float gh = 0.f, gt = 0.f;
    {
        int j = tid;
        for (; j + 3 * NT < CLS_NUM; j += 4 * NT) {
            float2 w1[4], w3[4];
#pragma unroll
            for (int u = 0; u < 4; u++) { w1[u] = __ldg(e1v + j + u * NT); }
#pragma unroll
            for (int u = 0; u < 4; u++) { w3[u] = __ldg(e3v + j + u * NT); }
#pragma unroll
            for (int u = 0; u < 4; u++) {
                float l1 = fmaf(a1, w1[u].x, b1c * w1[u].y);
                float l2 = fmaf(a3, w3[u].x, b3c * w3[u].y);
                float u2 = ex2(l2 - M2);
                float p1 = ex2(l1 - M1) * invZ1;
                float gap = fabsf(u2 * invZ2 - p1);
                int b = (int)((l2 - lo) * invw);
                b = max(0, min(NB - 1, b));
                if (b < b1)      gt += gap;
                else if (b > b1) gh += gap;
                else {
                    int s = (int)((l2 - lo1) * invw2);
                    s = max(0, min(NB - 1, s));
                    atomicAdd(&hist[s], u2);
                    int idx = atomicAdd(&s_cnt, 1);
                    if (idx < CAP) { st_l2[idx] = l2; st_u2[idx] = u2; st_gap[idx] = gap; }
                }
            }
        }
        for (; j < CLS_NUM; j += NT) {
            float2 v1 = __ldg(e1v + j);
            float2 v3 = __ldg(e3v + j);
            float l1 = fmaf(a1, v1.x, b1c * v1.y);
            float l2 = fmaf(a3, v3.x, b3c * v3.y);
            float u2 = ex2(l2 - M2);
            float p1 = ex2(l1 - M1) * invZ1;
            float gap = fabsf(u2 * invZ2 - p1);
            int b = (int)((l2 - lo) * invw);
            b = max(0, min(NB - 1, b));
            if (b < b1)      gt += gap;
            else if (b > b1) gh += gap;
            else {
                int s = (int)((l2 - lo1) * invw2);
                s = max(0, min(NB - 1, s));
                atomicAdd(&hist[s], u2);
                int idx = atomicAdd(&s_cnt, 1);
                if (idx < CAP) { st_l2[idx] = l2; st_u2[idx] = u2; st_gap[idx] = gap; }
            }
        }
    }

    // ---- Level-2 crossing within the sub-histogram
    find_crossing(hist, red, halfZ2 - cdf1, &s_b2, &s_cdf2);
    const int   b2   = s_b2;
    const float cdf2 = cdf1 + s_cdf2;   // mass strictly below the final sub-bin
    __syncthreads();
    const int m = s_cnt;   // uniform across block after sync

    if (m <= CAP) {
        // Classify stash by sub-bin (tie-break in final sub-bin by mass)
        for (int i = tid; i < m; i += NT) {
            int s = (int)((st_l2[i] - lo1) * invw2);
            s = max(0, min(NB - 1, s));
            bool tail;
            if (s != b2) tail = (s < b2);
            else         tail = (cdf2 + st_u2[i]) < halfZ2;
            if (tail) gt += st_gap[i]; else gh += st_gap[i];
        }
    } else {
        // Rare degenerate row (near-uniform teacher): exact global fallback
        // over the crossing-bin elements only.
        for (int j = tid; j < CLS_NUM; j += NT) {
            float2 v3 = __ldg(e3v + j);
            float l2 = fmaf(a3, v3.x, b3c * v3.y);
            int b = (int)((l2 - lo) * invw);
            b = max(0, min(NB - 1, b));
            if (b == b1) {
                float2 v1 = __ldg(e1v + j);
                float l1 = fmaf(a1, v1.x, b1c * v1.y);
                float u2 = ex2(l2 - M2);
                float p1 = ex2(l1 - M1) * invZ1;
                float gap = fabsf(u2 * invZ2 - p1);
                int s = (int)((l2 - lo1) * invw2);
                s = max(0, min(NB - 1, s));
                bool tail;
                if (s != b2) tail = (s < b2);
                else         tail = (cdf2 + u2) < halfZ2;
                if (tail) gt += gap; else gh += gap;
            }
        }
    }
    gh = block_sum(gh, red);
    gt = block_sum(gt, red);

    if (tid == 0) {
        // log2-domain sums -> nats
        float C21 = LN2 * (M2 - M1) + (__logf(Z2) - __logf(Z1));
        float fkl = LN2 * S2 / Z2 - C21;
        float rkl = LN2 * S1 / Z1 + C21;
        float denom = gh + gt;
        float akl = (gh * fkl + gt * rkl) / denom;
        atomicAdd(out, akl * (1.0f / (float)DATA_NUM));
    }
}

// ---------------------------------------------------------------------------
extern "C" void kernel_launch(void* const* d_in, const int* in_sizes, int n_in,
                              void* d_out, int out_size) {
    const float *h1 = 0, *h3 = 0, *e1 = 0, *e3 = 0;
    for (int i = 0; i < n_in; i++) {
        int s = in_sizes[i];
        if (s == 2 * DATA_NUM || s == 2 * DATA_NUM * 4) {
            if (!h1) h1 = (const float*)d_in[i]; else if (!h3) h3 = (const float*)d_in[i];
        } else if (s == 2 * CLS_NUM || s == 2 * CLS_NUM * 4) {
            if (!e1) e1 = (const float*)d_in[i]; else if (!e3) e3 = (const float*)d_in[i];
        }
    }
    if (!h1 || !h3 || !e1 || !e3) {
        h1 = (const float*)d_in[0];
        e1 = (const float*)d_in[1];
        h3 = (const float*)d_in[2];
        e3 = (const float*)d_in[3];
    }

    float* out = (float*)d_out;
    zero_out<<<1, 1>>>(out);
    akl_kernel<<<DATA_NUM, NT>>>(h1, e1, h3, e3, out);
}